// round 1
// baseline (speedup 1.0000x reference)
#include <cuda_runtime.h>

// Partials scratch: one float per block of the main kernel.
// N=16384 rows, 8 warps(rows)/block -> 2048 blocks. Sized generously.
__device__ float g_partials[8192];

#define WARPS_PER_BLOCK 8
#define D 1024                 // feature dim (fixed by problem)
#define VEC_PER_LANE (D / 4 / 32)   // 8 float4 per lane per matrix

__global__ __launch_bounds__(WARPS_PER_BLOCK * 32)
void cos_row_kernel(const float* __restrict__ a,
                    const float* __restrict__ b,
                    int n_rows) {
    const int lane  = threadIdx.x & 31;
    const int wid   = threadIdx.x >> 5;
    const int row   = blockIdx.x * WARPS_PER_BLOCK + wid;

    float s_ab = 0.f, s_aa = 0.f, s_bb = 0.f;

    if (row < n_rows) {
        const float4* __restrict__ a4 = reinterpret_cast<const float4*>(a) + (size_t)row * (D / 4);
        const float4* __restrict__ b4 = reinterpret_cast<const float4*>(b) + (size_t)row * (D / 4);

        // Front-batch independent loads for MLP, then FMA.
        float4 av[VEC_PER_LANE], bv[VEC_PER_LANE];
#pragma unroll
        for (int i = 0; i < VEC_PER_LANE; i++) {
            av[i] = a4[lane + 32 * i];
            bv[i] = b4[lane + 32 * i];
        }
#pragma unroll
        for (int i = 0; i < VEC_PER_LANE; i++) {
            s_ab = fmaf(av[i].x, bv[i].x, s_ab);
            s_ab = fmaf(av[i].y, bv[i].y, s_ab);
            s_ab = fmaf(av[i].z, bv[i].z, s_ab);
            s_ab = fmaf(av[i].w, bv[i].w, s_ab);

            s_aa = fmaf(av[i].x, av[i].x, s_aa);
            s_aa = fmaf(av[i].y, av[i].y, s_aa);
            s_aa = fmaf(av[i].z, av[i].z, s_aa);
            s_aa = fmaf(av[i].w, av[i].w, s_aa);

            s_bb = fmaf(bv[i].x, bv[i].x, s_bb);
            s_bb = fmaf(bv[i].y, bv[i].y, s_bb);
            s_bb = fmaf(bv[i].z, bv[i].z, s_bb);
            s_bb = fmaf(bv[i].w, bv[i].w, s_bb);
        }
    }

    // Warp reductions (3 values)
#pragma unroll
    for (int off = 16; off > 0; off >>= 1) {
        s_ab += __shfl_down_sync(0xFFFFFFFFu, s_ab, off);
        s_aa += __shfl_down_sync(0xFFFFFFFFu, s_aa, off);
        s_bb += __shfl_down_sync(0xFFFFFFFFu, s_bb, off);
    }

    __shared__ float sm[WARPS_PER_BLOCK];
    if (lane == 0) {
        float val = 0.f;
        if (row < n_rows) {
            const float na = fmaxf(sqrtf(s_aa), 1e-12f);
            const float nb = fmaxf(sqrtf(s_bb), 1e-12f);
            val = 1.0f - s_ab / (na * nb);
        }
        sm[wid] = val;
    }
    __syncthreads();

    if (wid == 0) {
        float v = (lane < WARPS_PER_BLOCK) ? sm[lane] : 0.f;
#pragma unroll
        for (int off = 16; off > 0; off >>= 1)
            v += __shfl_down_sync(0xFFFFFFFFu, v, off);
        if (lane == 0)
            g_partials[blockIdx.x] = v;
    }
}

// Deterministic final reduction of n_partials block sums; writes mean to out.
__global__ void final_reduce_kernel(float* __restrict__ out, int n_partials, float inv_n) {
    __shared__ float sm[32];
    const int tid  = threadIdx.x;
    const int lane = tid & 31;
    const int wid  = tid >> 5;

    float v = 0.f;
    for (int i = tid; i < n_partials; i += blockDim.x)
        v += g_partials[i];

#pragma unroll
    for (int off = 16; off > 0; off >>= 1)
        v += __shfl_down_sync(0xFFFFFFFFu, v, off);
    if (lane == 0) sm[wid] = v;
    __syncthreads();

    if (wid == 0) {
        v = (lane < (blockDim.x >> 5)) ? sm[lane] : 0.f;
#pragma unroll
        for (int off = 16; off > 0; off >>= 1)
            v += __shfl_down_sync(0xFFFFFFFFu, v, off);
        if (lane == 0) out[0] = v * inv_n;
    }
}

extern "C" void kernel_launch(void* const* d_in, const int* in_sizes, int n_in,
                              void* d_out, int out_size) {
    const float* a = (const float*)d_in[0];
    const float* b = (const float*)d_in[1];
    float* out = (float*)d_out;

    const int n_rows = in_sizes[0] / D;                   // 16384
    const int blocks = (n_rows + WARPS_PER_BLOCK - 1) / WARPS_PER_BLOCK;  // 2048

    cos_row_kernel<<<blocks, WARPS_PER_BLOCK * 32>>>(a, b, n_rows);
    final_reduce_kernel<<<1, 1024>>>(out, blocks, 1.0f / (float)n_rows);
}

// round 2
// speedup vs baseline: 1.0448x; 1.0448x over previous
#include <cuda_runtime.h>

// Partials scratch: one float per block of the main kernel.
// N=16384 rows, 8 warps(rows)/block -> 2048 blocks. Sized generously.
__device__ float g_partials[8192];

#define WARPS_PER_BLOCK 8
#define D 1024                 // feature dim (fixed by problem)
#define VEC_PER_LANE (D / 4 / 32)   // 8 float4 per lane per matrix

__global__ __launch_bounds__(WARPS_PER_BLOCK * 32)
void cos_row_kernel(const float* __restrict__ a,
                    const float* __restrict__ b,
                    int n_rows) {
    const int lane  = threadIdx.x & 31;
    const int wid   = threadIdx.x >> 5;
    const int row   = blockIdx.x * WARPS_PER_BLOCK + wid;

    float s_ab = 0.f, s_aa = 0.f, s_bb = 0.f;

    if (row < n_rows) {
        const float4* __restrict__ a4 = reinterpret_cast<const float4*>(a) + (size_t)row * (D / 4);
        const float4* __restrict__ b4 = reinterpret_cast<const float4*>(b) + (size_t)row * (D / 4);

        // Front-batch independent loads for MLP, then FMA.
        float4 av[VEC_PER_LANE], bv[VEC_PER_LANE];
#pragma unroll
        for (int i = 0; i < VEC_PER_LANE; i++) {
            av[i] = a4[lane + 32 * i];
            bv[i] = b4[lane + 32 * i];
        }
#pragma unroll
        for (int i = 0; i < VEC_PER_LANE; i++) {
            s_ab = fmaf(av[i].x, bv[i].x, s_ab);
            s_ab = fmaf(av[i].y, bv[i].y, s_ab);
            s_ab = fmaf(av[i].z, bv[i].z, s_ab);
            s_ab = fmaf(av[i].w, bv[i].w, s_ab);

            s_aa = fmaf(av[i].x, av[i].x, s_aa);
            s_aa = fmaf(av[i].y, av[i].y, s_aa);
            s_aa = fmaf(av[i].z, av[i].z, s_aa);
            s_aa = fmaf(av[i].w, av[i].w, s_aa);

            s_bb = fmaf(bv[i].x, bv[i].x, s_bb);
            s_bb = fmaf(bv[i].y, bv[i].y, s_bb);
            s_bb = fmaf(bv[i].z, bv[i].z, s_bb);
            s_bb = fmaf(bv[i].w, bv[i].w, s_bb);
        }
    }

    // Warp reductions (3 values)
#pragma unroll
    for (int off = 16; off > 0; off >>= 1) {
        s_ab += __shfl_down_sync(0xFFFFFFFFu, s_ab, off);
        s_aa += __shfl_down_sync(0xFFFFFFFFu, s_aa, off);
        s_bb += __shfl_down_sync(0xFFFFFFFFu, s_bb, off);
    }

    __shared__ float sm[WARPS_PER_BLOCK];
    if (lane == 0) {
        float val = 0.f;
        if (row < n_rows) {
            const float na = fmaxf(sqrtf(s_aa), 1e-12f);
            const float nb = fmaxf(sqrtf(s_bb), 1e-12f);
            val = 1.0f - s_ab / (na * nb);
        }
        sm[wid] = val;
    }
    __syncthreads();

    if (wid == 0) {
        float v = (lane < WARPS_PER_BLOCK) ? sm[lane] : 0.f;
#pragma unroll
        for (int off = 16; off > 0; off >>= 1)
            v += __shfl_down_sync(0xFFFFFFFFu, v, off);
        if (lane == 0)
            g_partials[blockIdx.x] = v;
    }
}

// Deterministic final reduction of n_partials block sums; writes mean to out.
__global__ void final_reduce_kernel(float* __restrict__ out, int n_partials, float inv_n) {
    __shared__ float sm[32];
    const int tid  = threadIdx.x;
    const int lane = tid & 31;
    const int wid  = tid >> 5;

    float v = 0.f;
    for (int i = tid; i < n_partials; i += blockDim.x)
        v += g_partials[i];

#pragma unroll
    for (int off = 16; off > 0; off >>= 1)
        v += __shfl_down_sync(0xFFFFFFFFu, v, off);
    if (lane == 0) sm[wid] = v;
    __syncthreads();

    if (wid == 0) {
        v = (lane < (blockDim.x >> 5)) ? sm[lane] : 0.f;
#pragma unroll
        for (int off = 16; off > 0; off >>= 1)
            v += __shfl_down_sync(0xFFFFFFFFu, v, off);
        if (lane == 0) out[0] = v * inv_n;
    }
}

extern "C" void kernel_launch(void* const* d_in, const int* in_sizes, int n_in,
                              void* d_out, int out_size) {
    const float* a = (const float*)d_in[0];
    const float* b = (const float*)d_in[1];
    float* out = (float*)d_out;

    const int n_rows = in_sizes[0] / D;                   // 16384
    const int blocks = (n_rows + WARPS_PER_BLOCK - 1) / WARPS_PER_BLOCK;  // 2048

    cos_row_kernel<<<blocks, WARPS_PER_BLOCK * 32>>>(a, b, n_rows);
    final_reduce_kernel<<<1, 1024>>>(out, blocks, 1.0f / (float)n_rows);
}